// round 2
// baseline (speedup 1.0000x reference)
#include <cuda_runtime.h>

// ---------------------------------------------------------------------------
// Fully-fused recurrent relational network, v2.
// One CTA = 4 graphs (32 node rows), 256 threads. h/x/A/B resident in 64KB smem.
// Thread tile: 2 rows x 8 cols. Packed fma.rn.f32x2 throughout.
// A/B message GEMMs fused into a single k-loop (shared activation loads).
// ---------------------------------------------------------------------------

#define THREADS 256
#define NG      4      // graphs per CTA
#define MROWS   32     // 8 * NG node rows per CTA
#define BS      2048
#define NSTEPS  8
#define H       128

union F2 { float2 f; unsigned long long u; };

__device__ __forceinline__ F2 f2fma(F2 a, F2 b, F2 c) {
    F2 d;
    asm("fma.rn.f32x2 %0, %1, %2, %3;" : "=l"(d.u) : "l"(a.u), "l"(b.u), "l"(c.u));
    return d;
}

__device__ __forceinline__ F2 f2bcast(float x) {
    F2 r; unsigned xi = __float_as_uint(x);
    asm("mov.b64 %0, {%1, %1};" : "=l"(r.u) : "r"(xi));
    return r;
}

// Load 8 consecutive floats (2x float4) as 4 packed F2 register pairs.
__device__ __forceinline__ void ld4(F2 (&w)[4], const float* __restrict__ p) {
    float4 w0 = *reinterpret_cast<const float4*>(p);
    float4 w1 = *reinterpret_cast<const float4*>(p + 4);
    w[0].f = make_float2(w0.x, w0.y);
    w[1].f = make_float2(w0.z, w0.w);
    w[2].f = make_float2(w1.x, w1.y);
    w[3].f = make_float2(w1.z, w1.w);
}

// acc[2 rows][4 col-pairs] += in[r0..r0+1][:] @ W   (W row-major 128 x 128)
__device__ __forceinline__ void gemm_acc(const float* __restrict__ in,
                                         const float* __restrict__ W,
                                         F2 (&acc)[2][4], int r0, int c0) {
#pragma unroll 2
    for (int kk = 0; kk < H; kk += 4) {
        float4 a0 = *reinterpret_cast<const float4*>(in + r0 * H + kk);
        float4 a1 = *reinterpret_cast<const float4*>(in + (r0 + 1) * H + kk);
        const float a0v[4] = {a0.x, a0.y, a0.z, a0.w};
        const float a1v[4] = {a1.x, a1.y, a1.z, a1.w};
#pragma unroll
        for (int k = 0; k < 4; ++k) {
            F2 w[4];
            ld4(w, W + (kk + k) * H + c0);
            F2 b0 = f2bcast(a0v[k]);
            F2 b1 = f2bcast(a1v[k]);
#pragma unroll
            for (int p = 0; p < 4; ++p) {
                acc[0][p] = f2fma(b0, w[p], acc[0][p]);
                acc[1][p] = f2fma(b1, w[p], acc[1][p]);
            }
        }
    }
}

// Fused: accA += in @ Wa ; accB += in @ Wb  (shared activation loads)
__device__ __forceinline__ void gemm_acc_dual(const float* __restrict__ in,
                                              const float* __restrict__ Wa,
                                              const float* __restrict__ Wb,
                                              F2 (&accA)[2][4], F2 (&accB)[2][4],
                                              int r0, int c0) {
    for (int kk = 0; kk < H; kk += 4) {
        float4 a0 = *reinterpret_cast<const float4*>(in + r0 * H + kk);
        float4 a1 = *reinterpret_cast<const float4*>(in + (r0 + 1) * H + kk);
        const float a0v[4] = {a0.x, a0.y, a0.z, a0.w};
        const float a1v[4] = {a1.x, a1.y, a1.z, a1.w};
#pragma unroll
        for (int k = 0; k < 4; ++k) {
            F2 wa[4], wb[4];
            ld4(wa, Wa + (kk + k) * H + c0);
            ld4(wb, Wb + (kk + k) * H + c0);
            F2 b0 = f2bcast(a0v[k]);
            F2 b1 = f2bcast(a1v[k]);
#pragma unroll
            for (int p = 0; p < 4; ++p) {
                accA[0][p] = f2fma(b0, wa[p], accA[0][p]);
                accA[1][p] = f2fma(b1, wa[p], accA[1][p]);
                accB[0][p] = f2fma(b0, wb[p], accB[0][p]);
                accB[1][p] = f2fma(b1, wb[p], accB[1][p]);
            }
        }
    }
}

__device__ __forceinline__ void acc_zero(F2 (&acc)[2][4]) {
#pragma unroll
    for (int r = 0; r < 2; ++r)
#pragma unroll
        for (int p = 0; p < 4; ++p) { acc[r][p].f.x = 0.f; acc[r][p].f.y = 0.f; }
}

__device__ __forceinline__ void acc_bias(F2 (&acc)[2][4], const float* __restrict__ bias,
                                         int c0, float scale) {
#pragma unroll
    for (int p = 0; p < 4; ++p) {
        float2 b = *reinterpret_cast<const float2*>(bias + c0 + 2 * p);
        F2 v; v.f.x = b.x * scale; v.f.y = b.y * scale;
        acc[0][p] = v;
        acc[1][p] = v;
    }
}

__device__ __forceinline__ void acc_store(float* __restrict__ out, F2 (&acc)[2][4],
                                          int r0, int c0, bool relu) {
#pragma unroll
    for (int r = 0; r < 2; ++r)
#pragma unroll
        for (int p = 0; p < 4; ++p) {
            float2 v = acc[r][p].f;
            if (relu) { v.x = fmaxf(v.x, 0.f); v.y = fmaxf(v.y, 0.f); }
            *reinterpret_cast<float2*>(out + (r0 + r) * H + c0 + 2 * p) = v;
        }
}

__global__ void __launch_bounds__(THREADS, 3)
rrn_kernel(const int* __restrict__ sources, const int* __restrict__ targets,
           const int* __restrict__ types, const int* __restrict__ diffs,
           const int* __restrict__ question,
           const float* __restrict__ pre_w1, const float* __restrict__ pre_b1,
           const float* __restrict__ pre_w2, const float* __restrict__ pre_b2,
           const float* __restrict__ msg_w1, const float* __restrict__ msg_b1,
           const float* __restrict__ msg_w2, const float* __restrict__ msg_b2,
           const float* __restrict__ node_w1, const float* __restrict__ node_b1,
           const float* __restrict__ node_w2, const float* __restrict__ node_b2,
           const float* __restrict__ out_w1, const float* __restrict__ out_b1,
           const float* __restrict__ out_w2, const float* __restrict__ out_b2,
           float* __restrict__ out)
{
    extern __shared__ float sm[];
    float* sh_h = sm;
    float* sh_x = sm + MROWS * H;
    float* sh_A = sm + 2 * MROWS * H;
    float* sh_B = sm + 3 * MROWS * H;

    const int t   = threadIdx.x;
    const int cta = blockIdx.x;
    const int c0  = (t & 15) * 8;   // 16 col-groups x 8 cols
    const int r0  = (t >> 4) * 2;   // 16 row-groups x 2 rows
    const int cl  = t & 127;        // column for elementwise stages
    const int hf  = t >> 7;         // 0/1: graph-pair selector

    // ---- pre-MLP hidden = relu(one-hot gather of pre_w1 rows + b1) -> sh_A
    {
        const float b1 = pre_b1[cl];
        for (int m = hf * 16; m < hf * 16 + 16; ++m) {
            const int node = cta * MROWS + m;
            const int b    = node >> 3;
            const int s    = sources[node];
            const int tg   = targets[node];
            const int ty   = types[node];
            const int d    = diffs[node];
            const int q    = question[b];
            float v = pre_w1[s * H + cl] + pre_w1[(8 + tg) * H + cl]
                    + pre_w1[(16 + ty) * H + cl] + pre_w1[(19 + d) * H + cl]
                    + pre_w1[(119 + q) * H + cl] + b1;
            sh_A[m * H + cl] = fmaxf(v, 0.f);
        }
    }
    __syncthreads();

    // ---- x = hidden @ pre_w2 + pre_b2 ;  h = x
    {
        F2 acc[2][4];
        acc_bias(acc, pre_b2, c0, 1.0f);
        gemm_acc(sh_A, pre_w2, acc, r0, c0);
        acc_store(sh_x, acc, r0, c0, false);
        acc_store(sh_h, acc, r0, c0, false);
    }
    __syncthreads();

    for (int step = 0; step < NSTEPS; ++step) {
        // A = h @ msg_w1[0:128] ; B = h @ msg_w1[128:256]  (fused)
        {
            F2 accA[2][4], accB[2][4];
            acc_zero(accA); acc_zero(accB);
            gemm_acc_dual(sh_h, msg_w1, msg_w1 + 128 * H, accA, accB, r0, c0);
            acc_store(sh_A, accA, r0, c0, false);
            acc_store(sh_B, accB, r0, c0, false);
        }
        __syncthreads();

        // S_i = sum_{j != i} relu(A_i + B_j + b1)   (in place into sh_A)
        {
            const float b1 = msg_b1[cl];
#pragma unroll
            for (int gg = 0; gg < 2; ++gg) {
                const int g = hf * 2 + gg;
                float bb[8];
#pragma unroll
                for (int j = 0; j < 8; ++j) bb[j] = sh_B[(g * 8 + j) * H + cl];
#pragma unroll
                for (int i = 0; i < 8; ++i) {
                    const float a = sh_A[(g * 8 + i) * H + cl];
                    float ssum = 0.f;
#pragma unroll
                    for (int j = 0; j < 8; ++j) ssum += fmaxf(a + bb[j] + b1, 0.f);
                    ssum -= fmaxf(a + bb[i] + b1, 0.f);  // drop self-edge
                    sh_A[(g * 8 + i) * H + cl] = ssum;
                }
            }
        }
        __syncthreads();

        // m_agg = S @ msg_w2 + 7*msg_b2  -> sh_B
        {
            F2 acc[2][4];
            acc_bias(acc, msg_b2, c0, 7.0f);
            gemm_acc(sh_A, msg_w2, acc, r0, c0);
            acc_store(sh_B, acc, r0, c0, false);
        }
        __syncthreads();

        // hidden = relu(x@Wn1a + h@Wn1b + magg@Wn1c + node_b1) -> sh_A
        {
            F2 acc[2][4];
            acc_bias(acc, node_b1, c0, 1.0f);
            gemm_acc(sh_x, node_w1,           acc, r0, c0);
            gemm_acc(sh_h, node_w1 + 128 * H, acc, r0, c0);
            gemm_acc(sh_B, node_w1 + 256 * H, acc, r0, c0);
            acc_store(sh_A, acc, r0, c0, true);
        }
        __syncthreads();

        // h_new = hidden @ node_w2 + node_b2 -> sh_h
        {
            F2 acc[2][4];
            acc_bias(acc, node_b2, c0, 1.0f);
            gemm_acc(sh_A, node_w2, acc, r0, c0);
            acc_store(sh_h, acc, r0, c0, false);
        }
        __syncthreads();

        // pooled[g] = sum over 8 nodes of h_new -> sh_B rows 0..3
        {
#pragma unroll
            for (int gg = 0; gg < 2; ++gg) {
                const int g = hf * 2 + gg;
                float p = 0.f;
#pragma unroll
                for (int v = 0; v < 8; ++v) p += sh_h[(g * 8 + v) * H + cl];
                sh_B[g * H + cl] = p;
            }
        }
        __syncthreads();

        // out hidden = relu(pooled @ out_w1 + out_b1) -> sh_B rows 4..7
        {
            float acc[2];
            const float ob = out_b1[cl];
            acc[0] = ob; acc[1] = ob;
#pragma unroll 4
            for (int k = 0; k < H; ++k) {
                const float w = out_w1[k * H + cl];
                acc[0] += sh_B[(hf * 2 + 0) * H + k] * w;
                acc[1] += sh_B[(hf * 2 + 1) * H + k] * w;
            }
            sh_B[(4 + hf * 2 + 0) * H + cl] = fmaxf(acc[0], 0.f);
            sh_B[(4 + hf * 2 + 1) * H + cl] = fmaxf(acc[1], 0.f);
        }
        __syncthreads();

        // logits = oh @ out_w2 + out_b2 -> gmem  (shape [step][bs][100])
        if (cl < 100) {
            const int j = cl;
            float acc[2];
            const float ob = out_b2[j];
            acc[0] = ob; acc[1] = ob;
#pragma unroll 4
            for (int k = 0; k < H; ++k) {
                const float w = out_w2[k * 100 + j];
                acc[0] += sh_B[(4 + hf * 2 + 0) * H + k] * w;
                acc[1] += sh_B[(4 + hf * 2 + 1) * H + k] * w;
            }
            out[(step * BS + cta * NG + hf * 2 + 0) * 100 + j] = acc[0];
            out[(step * BS + cta * NG + hf * 2 + 1) * 100 + j] = acc[1];
        }
        __syncthreads();   // protect sh_A/sh_B before next step's GEMM writes
    }
}

extern "C" void kernel_launch(void* const* d_in, const int* in_sizes, int n_in,
                              void* d_out, int out_size) {
    (void)in_sizes; (void)n_in; (void)out_size;
    const int*   sources  = (const int*)  d_in[0];
    const int*   targets  = (const int*)  d_in[1];
    const int*   types    = (const int*)  d_in[2];
    const int*   diffs    = (const int*)  d_in[3];
    const int*   question = (const int*)  d_in[4];
    const float* pre_w1   = (const float*)d_in[5];
    const float* pre_b1   = (const float*)d_in[6];
    const float* pre_w2   = (const float*)d_in[7];
    const float* pre_b2   = (const float*)d_in[8];
    const float* msg_w1   = (const float*)d_in[9];
    const float* msg_b1   = (const float*)d_in[10];
    const float* msg_w2   = (const float*)d_in[11];
    const float* msg_b2   = (const float*)d_in[12];
    const float* node_w1  = (const float*)d_in[13];
    const float* node_b1  = (const float*)d_in[14];
    const float* node_w2  = (const float*)d_in[15];
    const float* node_b2  = (const float*)d_in[16];
    const float* out_w1   = (const float*)d_in[17];
    const float* out_b1   = (const float*)d_in[18];
    const float* out_w2   = (const float*)d_in[19];
    const float* out_b2   = (const float*)d_in[20];

    const size_t smem = 4 * MROWS * H * sizeof(float);  // 64 KB
    cudaFuncSetAttribute(rrn_kernel, cudaFuncAttributeMaxDynamicSharedMemorySize,
                         (int)smem);

    rrn_kernel<<<BS / NG, THREADS, smem>>>(
        sources, targets, types, diffs, question,
        pre_w1, pre_b1, pre_w2, pre_b2,
        msg_w1, msg_b1, msg_w2, msg_b2,
        node_w1, node_b1, node_w2, node_b2,
        out_w1, out_b1, out_w2, out_b2,
        (float*)d_out);
}

// round 3
// speedup vs baseline: 3.5613x; 3.5613x over previous
#include <cuda_runtime.h>
#include <cstdint>

// ---------------------------------------------------------------------------
// Fully-fused recurrent relational network, v3.
// One CTA = 4 graphs (32 rows), 128 threads = 4 warps.
// Warp w owns rows w*8..w*8+7 ; lane owns cols lane*4..lane*4+3.
// Weights staged through smem via cp.async (double-buffered 16-k chunks):
// each weight matrix read from L2 exactly once per CTA per GEMM.
// xw = x @ node_w1[0:128] + node_b1 precomputed once (step-invariant).
// ---------------------------------------------------------------------------

#define THREADS 128
#define NG      4
#define MROWS   32
#define BS      2048
#define NSTEPS  8
#define H       128
#define KCH     16                      // k-rows per staged chunk
#define NCH     (H / KCH)               // 8 chunks per GEMM
#define CHF     (KCH * H)               // floats per chunk (2048 = 8KB)

union F2 { float2 f; unsigned long long u; };

__device__ __forceinline__ F2 f2fma(F2 a, F2 b, F2 c) {
    F2 d;
    asm("fma.rn.f32x2 %0, %1, %2, %3;" : "=l"(d.u) : "l"(a.u), "l"(b.u), "l"(c.u));
    return d;
}
__device__ __forceinline__ F2 f2bcast(float x) {
    F2 r; unsigned xi = __float_as_uint(x);
    asm("mov.b64 %0, {%1, %1};" : "=l"(r.u) : "r"(xi));
    return r;
}
__device__ __forceinline__ F2 f2mk(float x, float y) { F2 r; r.f.x = x; r.f.y = y; return r; }

__device__ __forceinline__ void cp_commit() { asm volatile("cp.async.commit_group;" ::: "memory"); }
__device__ __forceinline__ void cp_wait0()  { asm volatile("cp.async.wait_group 0;"  ::: "memory"); }

// Stage one 16x128 chunk of W into smem: 512 float4s, 4 per thread, coalesced.
__device__ __forceinline__ void stage_chunk(float* ws, const float* __restrict__ W,
                                            int chunk, int t) {
    const float4* src = reinterpret_cast<const float4*>(W + chunk * CHF) + t;
    unsigned dst = (unsigned)__cvta_generic_to_shared(ws) + t * 16;
#pragma unroll
    for (int i = 0; i < 4; ++i) {
        asm volatile("cp.async.cg.shared.global [%0], [%1], 16;"
                     :: "r"(dst + i * 128 * 16), "l"(src + i * 128) : "memory");
    }
}

__device__ __forceinline__ float f4c(const float4& v, int k) {
    return k == 0 ? v.x : k == 1 ? v.y : k == 2 ? v.z : v.w;
}

// acc[8 rows][2 F2] += in[r0..r0+7][:] @ W   (W streamed via smem double buffer)
__device__ __forceinline__ void gemm_run(const float* __restrict__ in,
                                         const float* __restrict__ W,
                                         F2 (&acc)[8][2], int r0, int c0, int t,
                                         float* ws0, float* ws1) {
    stage_chunk(ws0, W, 0, t);
    cp_commit();
    for (int ch = 0; ch < NCH; ++ch) {
        cp_wait0();
        __syncthreads();
        const float* wb = (ch & 1) ? ws1 : ws0;
        if (ch + 1 < NCH) {
            stage_chunk((ch & 1) ? ws0 : ws1, W, ch + 1, t);
            cp_commit();
        }
        const int kb = ch * KCH;
#pragma unroll
        for (int kk = 0; kk < KCH; kk += 4) {
            float4 a[8];
#pragma unroll
            for (int r = 0; r < 8; ++r)
                a[r] = *reinterpret_cast<const float4*>(in + (r0 + r) * H + kb + kk);
#pragma unroll
            for (int k = 0; k < 4; ++k) {
                float4 wv = *reinterpret_cast<const float4*>(wb + (kk + k) * H + c0);
                F2 w0 = f2mk(wv.x, wv.y), w1 = f2mk(wv.z, wv.w);
#pragma unroll
                for (int r = 0; r < 8; ++r) {
                    F2 b = f2bcast(f4c(a[r], k));
                    acc[r][0] = f2fma(b, w0, acc[r][0]);
                    acc[r][1] = f2fma(b, w1, acc[r][1]);
                }
            }
        }
    }
}

// Dual GEMM sharing activation loads: accA += in@Wa, accB += in@Wb.
__device__ __forceinline__ void gemm_dual(const float* __restrict__ in,
                                          const float* __restrict__ Wa,
                                          const float* __restrict__ Wb,
                                          F2 (&accA)[8][2], F2 (&accB)[8][2],
                                          int r0, int c0, int t,
                                          float* wsA0, float* wsA1,
                                          float* wsB0, float* wsB1) {
    stage_chunk(wsA0, Wa, 0, t);
    stage_chunk(wsB0, Wb, 0, t);
    cp_commit();
    for (int ch = 0; ch < NCH; ++ch) {
        cp_wait0();
        __syncthreads();
        const float* wa = (ch & 1) ? wsA1 : wsA0;
        const float* wbp = (ch & 1) ? wsB1 : wsB0;
        if (ch + 1 < NCH) {
            stage_chunk((ch & 1) ? wsA0 : wsA1, Wa, ch + 1, t);
            stage_chunk((ch & 1) ? wsB0 : wsB1, Wb, ch + 1, t);
            cp_commit();
        }
        const int kb = ch * KCH;
#pragma unroll
        for (int kk = 0; kk < KCH; kk += 4) {
            float4 a[8];
#pragma unroll
            for (int r = 0; r < 8; ++r)
                a[r] = *reinterpret_cast<const float4*>(in + (r0 + r) * H + kb + kk);
#pragma unroll
            for (int k = 0; k < 4; ++k) {
                float4 wva = *reinterpret_cast<const float4*>(wa + (kk + k) * H + c0);
                float4 wvb = *reinterpret_cast<const float4*>(wbp + (kk + k) * H + c0);
                F2 a0 = f2mk(wva.x, wva.y), a1 = f2mk(wva.z, wva.w);
                F2 b0 = f2mk(wvb.x, wvb.y), b1 = f2mk(wvb.z, wvb.w);
#pragma unroll
                for (int r = 0; r < 8; ++r) {
                    F2 b = f2bcast(f4c(a[r], k));
                    accA[r][0] = f2fma(b, a0, accA[r][0]);
                    accA[r][1] = f2fma(b, a1, accA[r][1]);
                    accB[r][0] = f2fma(b, b0, accB[r][0]);
                    accB[r][1] = f2fma(b, b1, accB[r][1]);
                }
            }
        }
    }
}

__device__ __forceinline__ void acc_zero(F2 (&acc)[8][2]) {
#pragma unroll
    for (int r = 0; r < 8; ++r) { acc[r][0] = f2mk(0.f, 0.f); acc[r][1] = f2mk(0.f, 0.f); }
}
__device__ __forceinline__ void acc_bias(F2 (&acc)[8][2], const float* __restrict__ bias,
                                         int c0, float s) {
    float4 b = *reinterpret_cast<const float4*>(bias + c0);
#pragma unroll
    for (int r = 0; r < 8; ++r) {
        acc[r][0] = f2mk(b.x * s, b.y * s);
        acc[r][1] = f2mk(b.z * s, b.w * s);
    }
}
__device__ __forceinline__ void acc_from_smem(F2 (&acc)[8][2], const float* __restrict__ src,
                                              int r0, int c0) {
#pragma unroll
    for (int r = 0; r < 8; ++r) {
        float4 v = *reinterpret_cast<const float4*>(src + (r0 + r) * H + c0);
        acc[r][0] = f2mk(v.x, v.y);
        acc[r][1] = f2mk(v.z, v.w);
    }
}
__device__ __forceinline__ void acc_store(float* __restrict__ out, F2 (&acc)[8][2],
                                          int r0, int c0, bool relu) {
#pragma unroll
    for (int r = 0; r < 8; ++r) {
        float4 v = make_float4(acc[r][0].f.x, acc[r][0].f.y, acc[r][1].f.x, acc[r][1].f.y);
        if (relu) {
            v.x = fmaxf(v.x, 0.f); v.y = fmaxf(v.y, 0.f);
            v.z = fmaxf(v.z, 0.f); v.w = fmaxf(v.w, 0.f);
        }
        *reinterpret_cast<float4*>(out + (r0 + r) * H + c0) = v;
    }
}

__global__ void __launch_bounds__(THREADS)
rrn_kernel(const int* __restrict__ sources, const int* __restrict__ targets,
           const int* __restrict__ types, const int* __restrict__ diffs,
           const int* __restrict__ question,
           const float* __restrict__ pre_w1, const float* __restrict__ pre_b1,
           const float* __restrict__ pre_w2, const float* __restrict__ pre_b2,
           const float* __restrict__ msg_w1, const float* __restrict__ msg_b1,
           const float* __restrict__ msg_w2, const float* __restrict__ msg_b2,
           const float* __restrict__ node_w1, const float* __restrict__ node_b1,
           const float* __restrict__ node_w2, const float* __restrict__ node_b2,
           const float* __restrict__ out_w1, const float* __restrict__ out_b1,
           const float* __restrict__ out_w2, const float* __restrict__ out_b2,
           float* __restrict__ out)
{
    extern __shared__ float sm[];
    float* sh_h  = sm;                    // h (current hidden state)
    float* sh_xw = sm + 4096;             // x @ node_w1[0:128] + node_b1 (precomputed)
    float* sh_A  = sm + 8192;             // scratch A / S / hidden
    float* sh_B  = sm + 12288;            // scratch B / m_agg / pooled
    float* ws0 = sm + 16384;              // W stage buffers (4 x 8KB)
    float* ws1 = ws0 + CHF;
    float* ws2 = ws1 + CHF;
    float* ws3 = ws2 + CHF;

    const int t    = threadIdx.x;
    const int cta  = blockIdx.x;
    const int warp = t >> 5;
    const int lane = t & 31;
    const int r0   = warp * 8;
    const int c0   = lane * 4;

    // ---- pre-MLP hidden = relu(one-hot gather of pre_w1 rows + b1) -> sh_A
    {
        const float b1 = pre_b1[t];
        for (int m = 0; m < MROWS; ++m) {
            const int node = cta * MROWS + m;
            const int b  = node >> 3;
            const int s  = sources[node];
            const int tg = targets[node];
            const int ty = types[node];
            const int d  = diffs[node];
            const int q  = question[b];
            float v = pre_w1[s * H + t] + pre_w1[(8 + tg) * H + t]
                    + pre_w1[(16 + ty) * H + t] + pre_w1[(19 + d) * H + t]
                    + pre_w1[(119 + q) * H + t] + b1;
            sh_A[m * H + t] = fmaxf(v, 0.f);
        }
    }
    __syncthreads();

    // ---- x = hidden @ pre_w2 + pre_b2 -> sh_h  (h0 = x)
    {
        F2 acc[8][2];
        acc_bias(acc, pre_b2, c0, 1.0f);
        gemm_run(sh_A, pre_w2, acc, r0, c0, t, ws0, ws1);
        acc_store(sh_h, acc, r0, c0, false);
    }
    __syncthreads();

    // ---- xw = x @ node_w1[0:128] + node_b1 -> sh_xw  (step-invariant)
    {
        F2 acc[8][2];
        acc_bias(acc, node_b1, c0, 1.0f);
        gemm_run(sh_h, node_w1, acc, r0, c0, t, ws0, ws1);
        acc_store(sh_xw, acc, r0, c0, false);
    }
    __syncthreads();

    for (int step = 0; step < NSTEPS; ++step) {
        // A = h @ msg_w1[0:128] ; B = h @ msg_w1[128:256]
        {
            F2 accA[8][2], accB[8][2];
            acc_zero(accA); acc_zero(accB);
            gemm_dual(sh_h, msg_w1, msg_w1 + 128 * H, accA, accB, r0, c0, t,
                      ws0, ws1, ws2, ws3);
            acc_store(sh_A, accA, r0, c0, false);
            acc_store(sh_B, accB, r0, c0, false);
        }
        __syncthreads();

        // S_i = sum_{j != i} relu(A_i + B_j + b1)  (in place in sh_A)
        {
            const float b1 = msg_b1[t];
#pragma unroll
            for (int g = 0; g < NG; ++g) {
                float bb[8];
#pragma unroll
                for (int j = 0; j < 8; ++j) bb[j] = sh_B[(g * 8 + j) * H + t];
#pragma unroll
                for (int i = 0; i < 8; ++i) {
                    const float a = sh_A[(g * 8 + i) * H + t];
                    float ssum = 0.f;
#pragma unroll
                    for (int j = 0; j < 8; ++j) ssum += fmaxf(a + bb[j] + b1, 0.f);
                    ssum -= fmaxf(a + bb[i] + b1, 0.f);
                    sh_A[(g * 8 + i) * H + t] = ssum;
                }
            }
        }
        __syncthreads();

        // m_agg = S @ msg_w2 + 7*msg_b2 -> sh_B
        {
            F2 acc[8][2];
            acc_bias(acc, msg_b2, c0, 7.0f);
            gemm_run(sh_A, msg_w2, acc, r0, c0, t, ws0, ws1);
            acc_store(sh_B, acc, r0, c0, false);
        }
        __syncthreads();

        // hidden = relu(xw + h@Wn1b + m_agg@Wn1c) -> sh_A
        {
            F2 acc[8][2];
            acc_from_smem(acc, sh_xw, r0, c0);
            gemm_run(sh_h, node_w1 + 128 * H, acc, r0, c0, t, ws0, ws1);
            gemm_run(sh_B, node_w1 + 256 * H, acc, r0, c0, t, ws2, ws3);
            acc_store(sh_A, acc, r0, c0, true);
        }
        __syncthreads();

        // h_new = hidden @ node_w2 + node_b2 -> sh_h
        {
            F2 acc[8][2];
            acc_bias(acc, node_b2, c0, 1.0f);
            gemm_run(sh_A, node_w2, acc, r0, c0, t, ws0, ws1);
            acc_store(sh_h, acc, r0, c0, false);
        }
        __syncthreads();

        // pooled[g] = sum over 8 nodes of h_new -> sh_B rows 0..3
        {
#pragma unroll
            for (int g = 0; g < NG; ++g) {
                float p = 0.f;
#pragma unroll
                for (int v = 0; v < 8; ++v) p += sh_h[(g * 8 + v) * H + t];
                sh_B[g * H + t] = p;
            }
        }
        __syncthreads();

        // out hidden = relu(pooled @ out_w1 + out_b1) -> sh_B rows 4..7
        {
            float acc[NG];
            const float ob = out_b1[t];
#pragma unroll
            for (int g = 0; g < NG; ++g) acc[g] = ob;
#pragma unroll 8
            for (int k = 0; k < H; ++k) {
                const float w = out_w1[k * H + t];
#pragma unroll
                for (int g = 0; g < NG; ++g) acc[g] += sh_B[g * H + k] * w;
            }
#pragma unroll
            for (int g = 0; g < NG; ++g) sh_B[(4 + g) * H + t] = fmaxf(acc[g], 0.f);
        }
        __syncthreads();

        // logits = oh @ out_w2 + out_b2 -> gmem [step][bs][100]
        if (t < 100) {
            float acc[NG];
            const float ob = out_b2[t];
#pragma unroll
            for (int g = 0; g < NG; ++g) acc[g] = ob;
#pragma unroll 8
            for (int k = 0; k < H; ++k) {
                const float w = out_w2[k * 100 + t];
#pragma unroll
                for (int g = 0; g < NG; ++g) acc[g] += sh_B[(4 + g) * H + k] * w;
            }
#pragma unroll
            for (int g = 0; g < NG; ++g)
                out[(step * BS + cta * NG + g) * 100 + t] = acc[g];
        }
        __syncthreads();   // sh_A/sh_B reused by next step's GEMMs
    }
}

extern "C" void kernel_launch(void* const* d_in, const int* in_sizes, int n_in,
                              void* d_out, int out_size) {
    (void)in_sizes; (void)n_in; (void)out_size;
    const int*   sources  = (const int*)  d_in[0];
    const int*   targets  = (const int*)  d_in[1];
    const int*   types    = (const int*)  d_in[2];
    const int*   diffs    = (const int*)  d_in[3];
    const int*   question = (const int*)  d_in[4];
    const float* pre_w1   = (const float*)d_in[5];
    const float* pre_b1   = (const float*)d_in[6];
    const float* pre_w2   = (const float*)d_in[7];
    const float* pre_b2   = (const float*)d_in[8];
    const float* msg_w1   = (const float*)d_in[9];
    const float* msg_b1   = (const float*)d_in[10];
    const float* msg_w2   = (const float*)d_in[11];
    const float* msg_b2   = (const float*)d_in[12];
    const float* node_w1  = (const float*)d_in[13];
    const float* node_b1  = (const float*)d_in[14];
    const float* node_w2  = (const float*)d_in[15];
    const float* node_b2  = (const float*)d_in[16];
    const float* out_w1   = (const float*)d_in[17];
    const float* out_b1   = (const float*)d_in[18];
    const float* out_w2   = (const float*)d_in[19];
    const float* out_b2   = (const float*)d_in[20];

    const size_t smem = (16384 + 4 * CHF) * sizeof(float);  // 64KB act + 32KB W stage = 96KB
    cudaFuncSetAttribute(rrn_kernel, cudaFuncAttributeMaxDynamicSharedMemorySize,
                         (int)smem);

    rrn_kernel<<<BS / NG, THREADS, smem>>>(
        sources, targets, types, diffs, question,
        pre_w1, pre_b1, pre_w2, pre_b2,
        msg_w1, msg_b1, msg_w2, msg_b2,
        node_w1, node_b1, node_w2, node_b2,
        out_w1, out_b1, out_w2, out_b2,
        (float*)d_out);
}

// round 4
// speedup vs baseline: 3.6525x; 1.0256x over previous
#include <cuda_runtime.h>
#include <cstdint>

// ---------------------------------------------------------------------------
// Fully-fused recurrent relational network, v4.
// CTA = 4 graphs, 128 threads = 4 warps; warp w owns graph w (rows w*8..w*8+7),
// lane owns cols lane*4..lane*4+3.  A/B/S/pooling are warp-register-local.
// smem: h + xw + scratch (48KB) + 6x4KB cp.async W ring = 72KB -> 3 CTAs/SM.
// ---------------------------------------------------------------------------

#define THREADS 128
#define NG      4
#define MROWS   32
#define BS      2048
#define NSTEPS  8
#define H       128
#define KCH     8                       // k-rows per staged chunk
#define NCHK    (H / KCH)               // 16 chunks per GEMM
#define CHF     (KCH * H)               // 1024 floats = 4KB per chunk

union F2 { float2 f; unsigned long long u; };

__device__ __forceinline__ F2 f2fma(F2 a, F2 b, F2 c) {
    F2 d;
    asm("fma.rn.f32x2 %0, %1, %2, %3;" : "=l"(d.u) : "l"(a.u), "l"(b.u), "l"(c.u));
    return d;
}
__device__ __forceinline__ F2 f2bcast(float x) {
    F2 r; unsigned xi = __float_as_uint(x);
    asm("mov.b64 %0, {%1, %1};" : "=l"(r.u) : "r"(xi));
    return r;
}
__device__ __forceinline__ F2 f2mk(float x, float y) { F2 r; r.f.x = x; r.f.y = y; return r; }

__device__ __forceinline__ void cp_commit() { asm volatile("cp.async.commit_group;" ::: "memory"); }
__device__ __forceinline__ void cp_wait1()  { asm volatile("cp.async.wait_group 1;"  ::: "memory"); }

__device__ __forceinline__ float f4c(const float4& v, int k) {
    return k == 0 ? v.x : k == 1 ? v.y : k == 2 ? v.z : v.w;
}

// Stage one 8x128 chunk (4KB): 256 float4, 2 per thread, coalesced.
__device__ __forceinline__ void stage_chunk(float* ws, const float* __restrict__ W,
                                            int chunk, int t) {
    const float4* src = reinterpret_cast<const float4*>(W + chunk * CHF) + t;
    unsigned dst = (unsigned)__cvta_generic_to_shared(ws) + t * 16;
#pragma unroll
    for (int i = 0; i < 2; ++i) {
        asm volatile("cp.async.cg.shared.global [%0], [%1], 16;"
                     :: "r"(dst + i * 2048), "l"(src + i * 128) : "memory");
    }
}

__device__ __forceinline__ void chunk_fma(const float* __restrict__ in,
                                          const float* __restrict__ wb,
                                          F2 (&acc)[8][2], int r0, int c0, int kb) {
#pragma unroll
    for (int kk = 0; kk < KCH; kk += 4) {
        float4 a[8];
#pragma unroll
        for (int r = 0; r < 8; ++r)
            a[r] = *reinterpret_cast<const float4*>(in + (r0 + r) * H + kb + kk);
#pragma unroll
        for (int k = 0; k < 4; ++k) {
            float4 wv = *reinterpret_cast<const float4*>(wb + (kk + k) * H + c0);
            F2 w0 = f2mk(wv.x, wv.y), w1 = f2mk(wv.z, wv.w);
#pragma unroll
            for (int r = 0; r < 8; ++r) {
                F2 b = f2bcast(f4c(a[r], k));
                acc[r][0] = f2fma(b, w0, acc[r][0]);
                acc[r][1] = f2fma(b, w1, acc[r][1]);
            }
        }
    }
}

__device__ __forceinline__ int ring_next2(int cur) { return cur + 2 >= 3 ? cur - 1 : cur + 2; }
__device__ __forceinline__ int ring_adv(int cur)   { return cur == 2 ? 0 : cur + 1; }

// acc += in(own rows) @ W, W streamed via 3-buffer cp.async ring (prefetch depth 2).
__device__ __forceinline__ void gemm_run(const float* __restrict__ in,
                                         const float* __restrict__ W,
                                         F2 (&acc)[8][2], int r0, int c0, int t,
                                         float* ws) {
    __syncthreads();                       // protect ring vs previous gemm's readers
    stage_chunk(ws, W, 0, t);            cp_commit();
    stage_chunk(ws + CHF, W, 1, t);      cp_commit();
    int cur = 0;
    for (int ch = 0; ch < NCHK; ++ch) {
        cp_wait1();
        __syncthreads();
        if (ch + 2 < NCHK) stage_chunk(ws + ring_next2(cur) * CHF, W, ch + 2, t);
        cp_commit();                       // empty group at tail keeps wait depth valid
        chunk_fma(in, ws + cur * CHF, acc, r0, c0, ch * KCH);
        cur = ring_adv(cur);
    }
}

// Dual GEMM sharing activation loads: accA += in@Wa ; accB += in@Wb.
__device__ __forceinline__ void gemm_dual(const float* __restrict__ in,
                                          const float* __restrict__ Wa,
                                          const float* __restrict__ Wb,
                                          F2 (&accA)[8][2], F2 (&accB)[8][2],
                                          int r0, int c0, int t,
                                          float* wsA, float* wsB) {
    __syncthreads();
    stage_chunk(wsA, Wa, 0, t); stage_chunk(wsB, Wb, 0, t); cp_commit();
    stage_chunk(wsA + CHF, Wa, 1, t); stage_chunk(wsB + CHF, Wb, 1, t); cp_commit();
    int cur = 0;
    for (int ch = 0; ch < NCHK; ++ch) {
        cp_wait1();
        __syncthreads();
        if (ch + 2 < NCHK) {
            stage_chunk(wsA + ring_next2(cur) * CHF, Wa, ch + 2, t);
            stage_chunk(wsB + ring_next2(cur) * CHF, Wb, ch + 2, t);
        }
        cp_commit();
        const float* wa = wsA + cur * CHF;
        const float* wbp = wsB + cur * CHF;
        const int kb = ch * KCH;
#pragma unroll
        for (int kk = 0; kk < KCH; kk += 4) {
            float4 a[8];
#pragma unroll
            for (int r = 0; r < 8; ++r)
                a[r] = *reinterpret_cast<const float4*>(in + (r0 + r) * H + kb + kk);
#pragma unroll
            for (int k = 0; k < 4; ++k) {
                float4 wva = *reinterpret_cast<const float4*>(wa + (kk + k) * H + c0);
                float4 wvb = *reinterpret_cast<const float4*>(wbp + (kk + k) * H + c0);
                F2 wa0 = f2mk(wva.x, wva.y), wa1 = f2mk(wva.z, wva.w);
                F2 wb0 = f2mk(wvb.x, wvb.y), wb1 = f2mk(wvb.z, wvb.w);
#pragma unroll
                for (int r = 0; r < 8; ++r) {
                    F2 b = f2bcast(f4c(a[r], k));
                    accA[r][0] = f2fma(b, wa0, accA[r][0]);
                    accA[r][1] = f2fma(b, wa1, accA[r][1]);
                    accB[r][0] = f2fma(b, wb0, accB[r][0]);
                    accB[r][1] = f2fma(b, wb1, accB[r][1]);
                }
            }
        }
        cur = ring_adv(cur);
    }
}

__device__ __forceinline__ void acc_zero(F2 (&acc)[8][2]) {
#pragma unroll
    for (int r = 0; r < 8; ++r) { acc[r][0] = f2mk(0.f, 0.f); acc[r][1] = f2mk(0.f, 0.f); }
}
__device__ __forceinline__ void acc_bias(F2 (&acc)[8][2], const float* __restrict__ bias,
                                         int c0, float s) {
    float4 b = *reinterpret_cast<const float4*>(bias + c0);
#pragma unroll
    for (int r = 0; r < 8; ++r) {
        acc[r][0] = f2mk(b.x * s, b.y * s);
        acc[r][1] = f2mk(b.z * s, b.w * s);
    }
}
__device__ __forceinline__ void acc_from_smem(F2 (&acc)[8][2], const float* __restrict__ src,
                                              int r0, int c0) {
#pragma unroll
    for (int r = 0; r < 8; ++r) {
        float4 v = *reinterpret_cast<const float4*>(src + (r0 + r) * H + c0);
        acc[r][0] = f2mk(v.x, v.y);
        acc[r][1] = f2mk(v.z, v.w);
    }
}
__device__ __forceinline__ void acc_store(float* __restrict__ out, F2 (&acc)[8][2],
                                          int r0, int c0, bool relu) {
#pragma unroll
    for (int r = 0; r < 8; ++r) {
        float4 v = make_float4(acc[r][0].f.x, acc[r][0].f.y, acc[r][1].f.x, acc[r][1].f.y);
        if (relu) {
            v.x = fmaxf(v.x, 0.f); v.y = fmaxf(v.y, 0.f);
            v.z = fmaxf(v.z, 0.f); v.w = fmaxf(v.w, 0.f);
        }
        *reinterpret_cast<float4*>(out + (r0 + r) * H + c0) = v;
    }
}

__global__ void __launch_bounds__(THREADS, 3)
rrn_kernel(const int* __restrict__ sources, const int* __restrict__ targets,
           const int* __restrict__ types, const int* __restrict__ diffs,
           const int* __restrict__ question,
           const float* __restrict__ pre_w1, const float* __restrict__ pre_b1,
           const float* __restrict__ pre_w2, const float* __restrict__ pre_b2,
           const float* __restrict__ msg_w1, const float* __restrict__ msg_b1,
           const float* __restrict__ msg_w2, const float* __restrict__ msg_b2,
           const float* __restrict__ node_w1, const float* __restrict__ node_b1,
           const float* __restrict__ node_w2, const float* __restrict__ node_b2,
           const float* __restrict__ out_w1, const float* __restrict__ out_b1,
           const float* __restrict__ out_w2, const float* __restrict__ out_b2,
           float* __restrict__ out)
{
    extern __shared__ float sm[];
    float* sh_h  = sm;                    // current hidden state
    float* sh_xw = sm + 4096;             // x @ node_w1[0:128] + node_b1 (step-invariant)
    float* sh_S  = sm + 8192;             // scratch: pre-feats / S / m_agg / hidden / pooled
    float* wsA   = sm + 12288;            // cp.async W ring: 2 streams x 3 bufs x 4KB
    float* wsB   = wsA + 3 * CHF;

    const int t    = threadIdx.x;
    const int cta  = blockIdx.x;
    const int warp = t >> 5;              // == graph within CTA
    const int r0   = warp * 8;
    const int c0   = (t & 31) * 4;

    // ---- pre-MLP hidden = relu(one-hot gather of pre_w1 rows + b1) -> sh_S
    {
        const float b1 = pre_b1[t];
        for (int m = 0; m < MROWS; ++m) {
            const int node = cta * MROWS + m;
            const int b  = node >> 3;
            const int s  = sources[node];
            const int tg = targets[node];
            const int ty = types[node];
            const int d  = diffs[node];
            const int q  = question[b];
            float v = pre_w1[s * H + t] + pre_w1[(8 + tg) * H + t]
                    + pre_w1[(16 + ty) * H + t] + pre_w1[(19 + d) * H + t]
                    + pre_w1[(119 + q) * H + t] + b1;
            sh_S[m * H + t] = fmaxf(v, 0.f);
        }
    }
    __syncthreads();

    // ---- x = hidden @ pre_w2 + pre_b2 -> sh_h  (h0 = x)
    {
        F2 acc[8][2];
        acc_bias(acc, pre_b2, c0, 1.0f);
        gemm_run(sh_S, pre_w2, acc, r0, c0, t, wsA);
        acc_store(sh_h, acc, r0, c0, false);
        __syncwarp();
    }

    // ---- xw = x @ node_w1[0:128] + node_b1 -> sh_xw
    {
        F2 acc[8][2];
        acc_bias(acc, node_b1, c0, 1.0f);
        gemm_run(sh_h, node_w1, acc, r0, c0, t, wsA);
        acc_store(sh_xw, acc, r0, c0, false);
        __syncwarp();
    }

    const float4 b1v = *reinterpret_cast<const float4*>(msg_b1 + c0);
    const float bias1[4] = {b1v.x, b1v.y, b1v.z, b1v.w};

    for (int step = 0; step < NSTEPS; ++step) {
        // A = h @ msg_w1[0:128] ; B = h @ msg_w1[128:256]  (reg-resident)
        F2 accA[8][2], accB[8][2];
        acc_zero(accA); acc_zero(accB);
        gemm_dual(sh_h, msg_w1, msg_w1 + 128 * H, accA, accB, r0, c0, t, wsA, wsB);

        // S_i = sum_{j != i} relu(A_i + B_j + b1)  (in registers, into accA)
        {
#pragma unroll
            for (int cc = 0; cc < 4; ++cc) {
                const int p = cc >> 1, hl = cc & 1;
                float A[8], Bv[8];
#pragma unroll
                for (int r = 0; r < 8; ++r) {
                    A[r]  = hl ? accA[r][p].f.y : accA[r][p].f.x;
                    Bv[r] = hl ? accB[r][p].f.y : accB[r][p].f.x;
                }
                const float bc = bias1[cc];
#pragma unroll
                for (int i = 0; i < 8; ++i) {
                    float s = 0.f;
#pragma unroll
                    for (int j = 0; j < 8; ++j) s += fmaxf(A[i] + Bv[j] + bc, 0.f);
                    s -= fmaxf(A[i] + Bv[i] + bc, 0.f);    // drop self-edge
                    if (hl) accA[i][p].f.y = s; else accA[i][p].f.x = s;
                }
            }
            acc_store(sh_S, accA, r0, c0, false);          // S -> smem (own rows)
            __syncwarp();
        }

        // m_agg = S @ msg_w2 + 7*msg_b2 -> sh_S (overwrite own rows)
        {
            F2 acc[8][2];
            acc_bias(acc, msg_b2, c0, 7.0f);
            gemm_run(sh_S, msg_w2, acc, r0, c0, t, wsA);
            acc_store(sh_S, acc, r0, c0, false);
            __syncwarp();
        }

        // hidden = relu(xw + h@Wn1b + m_agg@Wn1c) -> sh_S (own rows)
        {
            F2 acc[8][2];
            acc_from_smem(acc, sh_xw, r0, c0);
            gemm_run(sh_h, node_w1 + 128 * H, acc, r0, c0, t, wsA);
            gemm_run(sh_S, node_w1 + 256 * H, acc, r0, c0, t, wsB);
            acc_store(sh_S, acc, r0, c0, true);
            __syncwarp();
        }

        // h_new = hidden @ node_w2 + node_b2 -> sh_h ; pooled from regs
        {
            F2 acc[8][2];
            acc_bias(acc, node_b2, c0, 1.0f);
            gemm_run(sh_S, node_w2, acc, r0, c0, t, wsA);
            acc_store(sh_h, acc, r0, c0, false);
            float4 pool = make_float4(0.f, 0.f, 0.f, 0.f);
#pragma unroll
            for (int r = 0; r < 8; ++r) {
                pool.x += acc[r][0].f.x; pool.y += acc[r][0].f.y;
                pool.z += acc[r][1].f.x; pool.w += acc[r][1].f.y;
            }
            __syncthreads();               // all warps done reading sh_S rows
            *reinterpret_cast<float4*>(sh_S + warp * H + c0) = pool;  // pooled row = graph
        }
        __syncthreads();

        // out hidden = relu(pooled @ out_w1 + out_b1) -> sh_S rows 4..7
        {
            float acc[NG];
            const float ob = out_b1[t];
#pragma unroll
            for (int g = 0; g < NG; ++g) acc[g] = ob;
#pragma unroll 8
            for (int k = 0; k < H; ++k) {
                const float w = out_w1[k * H + t];
#pragma unroll
                for (int g = 0; g < NG; ++g) acc[g] += sh_S[g * H + k] * w;
            }
#pragma unroll
            for (int g = 0; g < NG; ++g) sh_S[(4 + g) * H + t] = fmaxf(acc[g], 0.f);
        }
        __syncthreads();

        // logits = oh @ out_w2 + out_b2 -> gmem [step][bs][100]
        if (t < 100) {
            float acc[NG];
            const float ob = out_b2[t];
#pragma unroll
            for (int g = 0; g < NG; ++g) acc[g] = ob;
#pragma unroll 8
            for (int k = 0; k < H; ++k) {
                const float w = out_w2[k * 100 + t];
#pragma unroll
                for (int g = 0; g < NG; ++g) acc[g] += sh_S[(4 + g) * H + k] * w;
            }
#pragma unroll
            for (int g = 0; g < NG; ++g)
                out[(step * BS + cta * NG + g) * 100 + t] = acc[g];
        }
        // next phase begins with gemm_dual's entry __syncthreads
    }
}

extern "C" void kernel_launch(void* const* d_in, const int* in_sizes, int n_in,
                              void* d_out, int out_size) {
    (void)in_sizes; (void)n_in; (void)out_size;
    const int*   sources  = (const int*)  d_in[0];
    const int*   targets  = (const int*)  d_in[1];
    const int*   types    = (const int*)  d_in[2];
    const int*   diffs    = (const int*)  d_in[3];
    const int*   question = (const int*)  d_in[4];
    const float* pre_w1   = (const float*)d_in[5];
    const float* pre_b1   = (const float*)d_in[6];
    const float* pre_w2   = (const float*)d_in[7];
    const float* pre_b2   = (const float*)d_in[8];
    const float* msg_w1   = (const float*)d_in[9];
    const float* msg_b1   = (const float*)d_in[10];
    const float* msg_w2   = (const float*)d_in[11];
    const float* msg_b2   = (const float*)d_in[12];
    const float* node_w1  = (const float*)d_in[13];
    const float* node_b1  = (const float*)d_in[14];
    const float* node_w2  = (const float*)d_in[15];
    const float* node_b2  = (const float*)d_in[16];
    const float* out_w1   = (const float*)d_in[17];
    const float* out_b1   = (const float*)d_in[18];
    const float* out_w2   = (const float*)d_in[19];
    const float* out_b2   = (const float*)d_in[20];

    const size_t smem = (3 * 4096 + 6 * CHF) * sizeof(float);  // 48KB + 24KB = 72KB
    cudaFuncSetAttribute(rrn_kernel, cudaFuncAttributeMaxDynamicSharedMemorySize,
                         (int)smem);

    rrn_kernel<<<BS / NG, THREADS, smem>>>(
        sources, targets, types, diffs, question,
        pre_w1, pre_b1, pre_w2, pre_b2,
        msg_w1, msg_b1, msg_w2, msg_b2,
        node_w1, node_b1, node_w2, node_b2,
        out_w1, out_b1, out_w2, out_b2,
        (float*)d_out);
}